// round 5
// baseline (speedup 1.0000x reference)
#include <cuda_runtime.h>
#include <cuda_bf16.h>
#include <stdint.h>

#define B_DIM 32
#define S_DIM 2048
#define MD 128
#define LB 64
#define NW 2041          // S - RANK + 1
#define WTILE 128
#define NTILES 512       // 32 batches x 16 chunks
#define AT_STRIDE 68     // u32 per row (136 bf16, pad -> conflict-free)

// Scratch (device globals: no allocations allowed)
__device__ float g_C64[LB * MD];   // C[w%64][m] = sum_n M[n][m]*Nk[l][n]
__device__ float g_G[MD * MD];     // G[m][m'] = sum_n M[n][m]*M[n][m']
__device__ float g_nksq[LB];
__device__ float g_part[NTILES];
__device__ unsigned int g_count;   // zero-init; reset by last block each call

// ---------------- K1: setup (prep + gram merged) -------------------
__global__ void k_setup(const float* __restrict__ M,
                        const float* __restrict__ A,
                        const float* __restrict__ Bb) {
    int t = threadIdx.x;   // 0..127
    if (blockIdx.x < LB) {
        int l = blockIdx.x;                 // 0..63
        __shared__ float nk[MD];
        __shared__ float red[MD];
        float v = A[t * LB + l] * Bb[l * MD + t];   // Nk[l][n=t]
        nk[t] = v;
        red[t] = v * v;
        __syncthreads();
        float c = 0.f;
#pragma unroll 8
        for (int n = 0; n < MD; n++) c += M[n * MD + t] * nk[n];
        g_C64[l * MD + t] = c;
        for (int s = 64; s > 0; s >>= 1) {
            if (t < s) red[t] += red[t + s];
            __syncthreads();
        }
        if (t == 0) g_nksq[l] = red[0];
    } else {
        int m = blockIdx.x - LB;            // 0..127
        float s = 0.f;
#pragma unroll 8
        for (int n = 0; n < MD; n++) s += M[n * MD + m] * M[n * MD + t];
        g_G[m * MD + t] = s;
    }
}

// ---------------- K2: main fused kernel --------------------
__global__ void __launch_bounds__(256, 3) k_main(const float* __restrict__ seq,
                                                 float* __restrict__ out) {
    __shared__ uint32_t At[MD * AT_STRIDE];   // [128][68] u32
    __shared__ float sred[8];
    __shared__ unsigned int s_ticket;

    int tid  = threadIdx.x;
    int lane = tid & 31;
    int wid  = tid >> 5;

    int tile  = blockIdx.x;
    int b     = tile >> 4;
    int chunk = tile & 15;
    int w0    = chunk * WTILE;
    int wt    = min(WTILE, NW - w0);

    // ---- phase 1: sliding-window agg (prefetch groups of 8) + cross ----
    float cross;
    {
        int m     = tid & 127;
        int wb    = (tid >> 7) * 64;        // 0 or 64
        int srow0 = w0 + wb;
        const float* sp = seq + ((size_t)b * S_DIM + srow0) * MD + m;

        float ring[8];
        float s = 0.f;
#pragma unroll
        for (int j = 0; j < 7; j++) { float x = sp[j * MD]; ring[j] = x; s += x; }

        float cr[4] = {0.f, 0.f, 0.f, 0.f};
        float aprev = 0.f;
#pragma unroll
        for (int wg = 0; wg < 64; wg += 8) {
            float nb[8];
#pragma unroll
            for (int j = 0; j < 8; j++) {
                int r = wg + 7 + j;
                nb[j] = (srow0 + r < S_DIM) ? sp[r * MD] : 0.f;
            }
#pragma unroll
            for (int j = 0; j < 8; j++) {
                int w = wg + j;
                s += nb[j];
                float a = (wb + w < wt) ? s * 0.125f : 0.f;
                cr[j & 3] += a * __ldg(&g_C64[w * MD + m]);  // (w0+wb+w)%64 == w
                s -= ring[w & 7];
                ring[(w + 7) & 7] = nb[j];
                if (j & 1) {
                    __nv_bfloat162 pk = __floats2bfloat162_rn(aprev, a);
                    At[m * AT_STRIDE + ((wb + w) >> 1)] =
                        *reinterpret_cast<uint32_t*>(&pk);
                } else {
                    aprev = a;
                }
            }
        }
        cross = (cr[0] + cr[1]) + (cr[2] + cr[3]);
    }
    __syncthreads();

    // ---- phase 2: Gram-halves via ldmatrix + mma, fused G-dot ----
    int wm = (wid & 3) << 5;   // m offset (4 warps along M)
    int wn = (wid >> 2) << 6;  // n offset (2 warps along N)
    int g  = lane >> 2;
    int tc = lane & 3;

    uint32_t at_u32 = (uint32_t)__cvta_generic_to_shared(At);
    // A-frag ldmatrix addresses (per mt): row = wm + mt*16 + (lane&15),
    // byte col = ((lane>>4)&1)*16 (+ ks*32 in loop)
    uint32_t a_addr[2];
#pragma unroll
    for (int mt = 0; mt < 2; mt++) {
        int row = wm + mt * 16 + (lane & 15);
        a_addr[mt] = at_u32 + row * (AT_STRIDE * 4) + ((lane >> 4) & 1) * 16;
    }

    float dot = 0.f;
#pragma unroll
    for (int h = 0; h < 2; h++) {
        int nbase = wn + h * 32;
        // B-frag ldmatrix addresses (per pair p covering nt=2p,2p+1)
        uint32_t b_addr[2];
#pragma unroll
        for (int p = 0; p < 2; p++) {
            int row = nbase + p * 16 + ((lane >> 4) & 1) * 8 + (lane & 7);
            b_addr[p] = at_u32 + row * (AT_STRIDE * 4) + ((lane >> 3) & 1) * 16;
        }

        float acc[2][4][4];
#pragma unroll
        for (int mt = 0; mt < 2; mt++)
#pragma unroll
            for (int nt = 0; nt < 4; nt++)
#pragma unroll
                for (int c = 0; c < 4; c++) acc[mt][nt][c] = 0.f;

#pragma unroll
        for (int ks = 0; ks < 8; ks++) {
            uint32_t af[2][4], bq[2][4];
#pragma unroll
            for (int mt = 0; mt < 2; mt++)
                asm volatile(
                    "ldmatrix.sync.aligned.m8n8.x4.shared.b16 {%0,%1,%2,%3}, [%4];"
                    : "=r"(af[mt][0]), "=r"(af[mt][1]),
                      "=r"(af[mt][2]), "=r"(af[mt][3])
                    : "r"(a_addr[mt] + ks * 32));
#pragma unroll
            for (int p = 0; p < 2; p++)
                asm volatile(
                    "ldmatrix.sync.aligned.m8n8.x4.shared.b16 {%0,%1,%2,%3}, [%4];"
                    : "=r"(bq[p][0]), "=r"(bq[p][1]),
                      "=r"(bq[p][2]), "=r"(bq[p][3])
                    : "r"(b_addr[p] + ks * 32));
#pragma unroll
            for (int nt = 0; nt < 4; nt++) {
                uint32_t b0 = bq[nt >> 1][(nt & 1) * 2];
                uint32_t b1 = bq[nt >> 1][(nt & 1) * 2 + 1];
#pragma unroll
                for (int mt = 0; mt < 2; mt++)
                    asm volatile(
                        "mma.sync.aligned.m16n8k16.row.col.f32.bf16.bf16.f32 "
                        "{%0,%1,%2,%3}, {%4,%5,%6,%7}, {%8,%9}, {%0,%1,%2,%3};"
                        : "+f"(acc[mt][nt][0]), "+f"(acc[mt][nt][1]),
                          "+f"(acc[mt][nt][2]), "+f"(acc[mt][nt][3])
                        : "r"(af[mt][0]), "r"(af[mt][1]),
                          "r"(af[mt][2]), "r"(af[mt][3]),
                          "r"(b0), "r"(b1));
            }
        }

        // epilogue for this half: dot partial Gram (registers) with G
#pragma unroll
        for (int mt = 0; mt < 2; mt++)
#pragma unroll
            for (int nt = 0; nt < 4; nt++) {
                int r = wm + mt * 16 + g;
                int c = nbase + nt * 8 + 2 * tc;
                float2 g0 = __ldg(reinterpret_cast<const float2*>(&g_G[r * MD + c]));
                float2 g1 = __ldg(reinterpret_cast<const float2*>(&g_G[(r + 8) * MD + c]));
                dot += acc[mt][nt][0] * g0.x + acc[mt][nt][1] * g0.y;
                dot += acc[mt][nt][2] * g1.x + acc[mt][nt][3] * g1.y;
            }
    }

    // ---- block reduce (dot - 2*cross) via shuffles ----
    float val = dot - 2.f * cross;
#pragma unroll
    for (int o = 16; o > 0; o >>= 1) val += __shfl_xor_sync(0xffffffffu, val, o);
    if (lane == 0) sred[wid] = val;
    __syncthreads();

    // ---- last-block final reduction (replay-safe ticket) ----
    if (tid == 0) {
        float t = 0.f;
#pragma unroll
        for (int i = 0; i < 8; i++) t += sred[i];
        g_part[blockIdx.x] = t;
        __threadfence();
        s_ticket = atomicAdd(&g_count, 1u);
    }
    __syncthreads();
    if (s_ticket == NTILES - 1) {
        float v = g_part[tid] + g_part[tid + 256];
        if (tid < LB) {
            int cnt = (NW - 1 - tid) / 64 + 1;   // #windows with w%64 == tid
            v += (float)B_DIM * (float)cnt * g_nksq[tid];
        }
#pragma unroll
        for (int o = 16; o > 0; o >>= 1) v += __shfl_xor_sync(0xffffffffu, v, o);
        if (lane == 0) sred[wid] = v;
        __syncthreads();
        if (tid == 0) {
            float t = 0.f;
#pragma unroll
            for (int i = 0; i < 8; i++) t += sred[i];
            out[0] = t * (float)(1.0 / (32.0 * 2041.0 * 128.0));
            g_count = 0u;   // reset for next graph replay
        }
    }
}

extern "C" void kernel_launch(void* const* d_in, const int* in_sizes, int n_in,
                              void* d_out, int out_size) {
    (void)in_sizes; (void)n_in; (void)out_size;
    const float* seq = (const float*)d_in[0];
    const float* M   = (const float*)d_in[1];
    const float* A   = (const float*)d_in[2];
    const float* Bb  = (const float*)d_in[3];
    float* out = (float*)d_out;

    k_setup<<<LB + MD, MD>>>(M, A, Bb);
    k_main<<<NTILES, 256>>>(seq, out);
}

// round 6
// speedup vs baseline: 1.6342x; 1.6342x over previous
#include <cuda_runtime.h>
#include <cuda_bf16.h>
#include <stdint.h>

#define B_DIM 32
#define S_DIM 2048
#define MD 128
#define LB 64
#define NW 2041          // S - RANK + 1
#define WTILE 128
#define NTILES 512       // 32 batches x 16 chunks
#define AT_STRIDE_U32 68 // 128 bf16 data + 8 bf16 pad = 272B row -> conflict-free

// Scratch (device globals: no allocations allowed)
__device__ float g_C64[LB * MD];   // C[w%64][m] = sum_n M[n][m]*Nk[l][n]
__device__ float g_G[MD * MD];     // G[m][m'] = sum_n M[n][m]*M[n][m']
__device__ float g_nksq[LB];
__device__ float g_part[NTILES];
__device__ unsigned int g_count;   // zero-init; reset by last block each call

// ---------------- K1: setup (prep + gram merged) -------------------
__global__ void k_setup(const float* __restrict__ M,
                        const float* __restrict__ A,
                        const float* __restrict__ Bb) {
    int t = threadIdx.x;   // 0..127
    if (blockIdx.x < LB) {
        int l = blockIdx.x;                 // 0..63
        __shared__ float nk[MD];
        __shared__ float red[MD];
        float v = A[t * LB + l] * Bb[l * MD + t];   // Nk[l][n=t]
        nk[t] = v;
        red[t] = v * v;
        __syncthreads();
        float c = 0.f;
#pragma unroll 8
        for (int n = 0; n < MD; n++) c += M[n * MD + t] * nk[n];
        g_C64[l * MD + t] = c;
        for (int s = 64; s > 0; s >>= 1) {
            if (t < s) red[t] += red[t + s];
            __syncthreads();
        }
        if (t == 0) g_nksq[l] = red[0];
    } else {
        int m = blockIdx.x - LB;            // 0..127
        float s = 0.f;
#pragma unroll 8
        for (int n = 0; n < MD; n++) s += M[n * MD + m] * M[n * MD + t];
        g_G[m * MD + t] = s;
    }
}

// ---------------- K2: main fused kernel --------------------
// At2 layout: [w][m]  w=0..127 rows of 128 bf16 (+pad), stride 272B.
__global__ void __launch_bounds__(256, 2) k_main(const float* __restrict__ seq,
                                                 float* __restrict__ out) {
    __shared__ uint32_t At2[WTILE * AT_STRIDE_U32];
    __shared__ float sred[8];
    __shared__ unsigned int s_ticket;

    int tid  = threadIdx.x;
    int lane = tid & 31;
    int wid  = tid >> 5;

    int tile  = blockIdx.x;
    int b     = tile >> 4;
    int chunk = tile & 15;
    int w0    = chunk * WTILE;
    int wt    = min(WTILE, NW - w0);

    // ---- phase 1: float4 sliding-window (prefix ring) + cross ----
    float cross;
    {
        int ws    = wid;                 // 16-window segment per warp
        int srow0 = w0 + ws * 16;
        const float4* g4 = reinterpret_cast<const float4*>(seq);
        size_t base = ((size_t)b * S_DIM + srow0) * 32 + lane;

        float4 run = make_float4(0.f, 0.f, 0.f, 0.f);
        float4 ring[8];
#pragma unroll
        for (int r = 0; r < 7; r++) {           // rows srow0..srow0+6 (<2048 always)
            ring[r] = run;
            float4 v = __ldg(&g4[base + (size_t)r * 32]);
            run.x += v.x; run.y += v.y; run.z += v.z; run.w += v.w;
        }
        ring[7] = run;  // placeholder (overwritten before use at j=7)

        float4 cr = make_float4(0.f, 0.f, 0.f, 0.f);
#pragma unroll
        for (int j = 0; j < 16; j++) {
            int r = j + 7;
            float4 v = make_float4(0.f, 0.f, 0.f, 0.f);
            if (srow0 + r < S_DIM) v = __ldg(&g4[base + (size_t)r * 32]);
            run.x += v.x; run.y += v.y; run.z += v.z; run.w += v.w;

            int wc = ws * 16 + j;        // window index within chunk
            float4 P0 = ring[j & 7];
            float4 a;
            if (wc < wt) {
                a.x = (run.x - P0.x) * 0.125f;
                a.y = (run.y - P0.y) * 0.125f;
                a.z = (run.z - P0.z) * 0.125f;
                a.w = (run.w - P0.w) * 0.125f;
            } else {
                a = make_float4(0.f, 0.f, 0.f, 0.f);
            }
            ring[j & 7] = run;

            float4 c = __ldg(reinterpret_cast<const float4*>(
                &g_C64[(wc & 63) * MD + lane * 4]));
            cr.x += a.x * c.x; cr.y += a.y * c.y;
            cr.z += a.z * c.z; cr.w += a.w * c.w;

            __nv_bfloat162 p0 = __floats2bfloat162_rn(a.x, a.y);
            __nv_bfloat162 p1 = __floats2bfloat162_rn(a.z, a.w);
            uint2 pk = make_uint2(*reinterpret_cast<uint32_t*>(&p0),
                                  *reinterpret_cast<uint32_t*>(&p1));
            *reinterpret_cast<uint2*>(&At2[wc * AT_STRIDE_U32 + lane * 2]) = pk;
        }
        cross = (cr.x + cr.y) + (cr.z + cr.w);
    }
    __syncthreads();

    // ---- phase 2: Gram via ldmatrix.trans + mma, fused G-dot ----
    int wm = (wid & 3) << 5;   // m offset (4 warps along M)
    int wn = (wid >> 2) << 6;  // n offset (2 warps along N)
    int g  = lane >> 2;
    int tc = lane & 3;

    float acc[2][8][4];
#pragma unroll
    for (int a = 0; a < 2; a++)
#pragma unroll
        for (int bb = 0; bb < 8; bb++)
#pragma unroll
            for (int c = 0; c < 4; c++) acc[a][bb][c] = 0.f;

    uint32_t at_base = (uint32_t)__cvta_generic_to_shared(At2);
    const int ROWB = AT_STRIDE_U32 * 4;   // 272 bytes per w-row

    // A x4.trans tile order: (m,k0),(m+8,k0),(m,k8),(m+8,k8)
    //   k row  = ((lane>>4)&1)*8 + (lane&7)
    //   m off  = ((lane>>3)&1)*8
    uint32_t a_addr[2];
    {
        int krow = ((lane >> 4) & 1) * 8 + (lane & 7);
        int moff = ((lane >> 3) & 1) * 8;
#pragma unroll
        for (int mt = 0; mt < 2; mt++)
            a_addr[mt] = at_base + krow * ROWB + (wm + mt * 16 + moff) * 2;
    }
    // B x4.trans tile order: (n,k0),(n,k8),(n+8,k0),(n+8,k8)
    //   k row  = ((lane>>3)&1)*8 + (lane&7)
    //   n off  = ((lane>>4)&1)*8
    uint32_t b_addr[4];
    {
        int krow = ((lane >> 3) & 1) * 8 + (lane & 7);
        int noff = ((lane >> 4) & 1) * 8;
#pragma unroll
        for (int nb = 0; nb < 4; nb++)
            b_addr[nb] = at_base + krow * ROWB + (wn + nb * 16 + noff) * 2;
    }

#pragma unroll
    for (int ks = 0; ks < 8; ks++) {
        uint32_t koff = ks * 16 * ROWB;
        uint32_t af[2][4], bq[4][4];
#pragma unroll
        for (int mt = 0; mt < 2; mt++)
            asm volatile(
                "ldmatrix.sync.aligned.m8n8.x4.trans.shared.b16 {%0,%1,%2,%3}, [%4];"
                : "=r"(af[mt][0]), "=r"(af[mt][1]),
                  "=r"(af[mt][2]), "=r"(af[mt][3])
                : "r"(a_addr[mt] + koff));
#pragma unroll
        for (int nb = 0; nb < 4; nb++)
            asm volatile(
                "ldmatrix.sync.aligned.m8n8.x4.trans.shared.b16 {%0,%1,%2,%3}, [%4];"
                : "=r"(bq[nb][0]), "=r"(bq[nb][1]),
                  "=r"(bq[nb][2]), "=r"(bq[nb][3])
                : "r"(b_addr[nb] + koff));
#pragma unroll
        for (int nt = 0; nt < 8; nt++) {
            uint32_t b0 = bq[nt >> 1][(nt & 1) * 2];
            uint32_t b1 = bq[nt >> 1][(nt & 1) * 2 + 1];
#pragma unroll
            for (int mt = 0; mt < 2; mt++)
                asm volatile(
                    "mma.sync.aligned.m16n8k16.row.col.f32.bf16.bf16.f32 "
                    "{%0,%1,%2,%3}, {%4,%5,%6,%7}, {%8,%9}, {%0,%1,%2,%3};"
                    : "+f"(acc[mt][nt][0]), "+f"(acc[mt][nt][1]),
                      "+f"(acc[mt][nt][2]), "+f"(acc[mt][nt][3])
                    : "r"(af[mt][0]), "r"(af[mt][1]),
                      "r"(af[mt][2]), "r"(af[mt][3]),
                      "r"(b0), "r"(b1));
        }
    }

    // ---- epilogue: dot partial Gram (registers) with G ----
    float dot = 0.f;
#pragma unroll
    for (int mt = 0; mt < 2; mt++)
#pragma unroll
        for (int nt = 0; nt < 8; nt++) {
            int r = wm + mt * 16 + g;
            int c = wn + nt * 8 + 2 * tc;
            float2 g0 = __ldg(reinterpret_cast<const float2*>(&g_G[r * MD + c]));
            float2 g1 = __ldg(reinterpret_cast<const float2*>(&g_G[(r + 8) * MD + c]));
            dot += acc[mt][nt][0] * g0.x + acc[mt][nt][1] * g0.y;
            dot += acc[mt][nt][2] * g1.x + acc[mt][nt][3] * g1.y;
        }

    // ---- block reduce (dot - 2*cross) via shuffles ----
    float val = dot - 2.f * cross;
#pragma unroll
    for (int o = 16; o > 0; o >>= 1) val += __shfl_xor_sync(0xffffffffu, val, o);
    if (lane == 0) sred[wid] = val;
    __syncthreads();

    // ---- last-block final reduction (replay-safe ticket) ----
    if (tid == 0) {
        float t = 0.f;
#pragma unroll
        for (int i = 0; i < 8; i++) t += sred[i];
        g_part[blockIdx.x] = t;
        __threadfence();
        s_ticket = atomicAdd(&g_count, 1u);
    }
    __syncthreads();
    if (s_ticket == NTILES - 1) {
        float v = g_part[tid] + g_part[tid + 256];
        if (tid < LB) {
            int cnt = (NW - 1 - tid) / 64 + 1;   // #windows with w%64 == tid
            v += (float)B_DIM * (float)cnt * g_nksq[tid];
        }
#pragma unroll
        for (int o = 16; o > 0; o >>= 1) v += __shfl_xor_sync(0xffffffffu, v, o);
        if (lane == 0) sred[wid] = v;
        __syncthreads();
        if (tid == 0) {
            float t = 0.f;
#pragma unroll
            for (int i = 0; i < 8; i++) t += sred[i];
            out[0] = t * (float)(1.0 / (32.0 * 2041.0 * 128.0));
            g_count = 0u;   // reset for next graph replay
        }
    }
}

extern "C" void kernel_launch(void* const* d_in, const int* in_sizes, int n_in,
                              void* d_out, int out_size) {
    (void)in_sizes; (void)n_in; (void)out_size;
    const float* seq = (const float*)d_in[0];
    const float* M   = (const float*)d_in[1];
    const float* A   = (const float*)d_in[2];
    const float* Bb  = (const float*)d_in[3];
    float* out = (float*)d_out;

    k_setup<<<LB + MD, MD>>>(M, A, Bb);
    k_main<<<NTILES, 256>>>(seq, out);
}